// round 16
// baseline (speedup 1.0000x reference)
#include <cuda_runtime.h>
#include <cstdint>

// ---------------- problem constants ----------------
#define E_TOTAL 500000
#define MT      128            // edges per CTA
#define NTH     256            // 8 warps, 2x4 warp grid (64x64 per warp)
#define PAN_BIG 8192           // words per [256n x 32k] tf32 panel (32KB, XOR-swizzled)
#define PAN_SM  2048           // words per [64n x 32k] panel (8KB)
#define SA_LD   68             // layer-1 A tile row stride (words)
#define SA_BUF  8704           // words per A tile buffer (128*68)
#define SH_LD   260            // H buffer row stride (words)

// pre-permuted+swizzled tf32 weight panels
__device__ __align__(16) unsigned g_Wp1[12 * PAN_BIG];
__device__ __align__(16) unsigned g_Wp2[8  * PAN_BIG];
__device__ __align__(16) unsigned g_Wp3[8  * PAN_SM];

struct __align__(16) Smem {
    unsigned H[MT * SH_LD];    // 133120B: h buffer; first 3*SA_BUF words alias A tiles
    unsigned Bp[2][PAN_BIG];   // 65536B : double-buffered weight panels
    float    red[MT][4][2];    // per-row per-warpcol (sum, sumsq)
    int      batch[MT];
    float    w0[MT], w1[MT], mu_[MT], rs_[MT];
    int      is64;
    float    Ww[256], bw[128], gw[128], betaw[128];
    float    b1[256], g1[256], be1[256];
    float    b2[256], g2[256], be2[256];
    float    b3[64];
};

__device__ __forceinline__ unsigned f2tf32(float x) {
    unsigned u;
    asm("cvt.rna.tf32.f32 %0, %1;" : "=r"(u) : "f"(x));
    return u;
}
__device__ __forceinline__ unsigned smem_u32(const void* p) {
    return (unsigned)__cvta_generic_to_shared(p);
}
__device__ __forceinline__ void mma8(float* d,
                                     unsigned a0, unsigned a1, unsigned a2, unsigned a3,
                                     unsigned b0, unsigned b1) {
    asm volatile(
        "mma.sync.aligned.m16n8k8.row.col.f32.tf32.tf32.f32 "
        "{%0,%1,%2,%3}, {%4,%5,%6,%7}, {%8,%9}, {%0,%1,%2,%3};"
        : "+f"(d[0]), "+f"(d[1]), "+f"(d[2]), "+f"(d[3])
        : "r"(a0), "r"(a1), "r"(a2), "r"(a3), "r"(b0), "r"(b1));
}

#define CPWAIT1()  asm volatile("cp.async.wait_group 1;" ::: "memory")
#define CPCOMMIT() asm volatile("cp.async.commit_group;" ::: "memory")
#define PAIRBAR(id) asm volatile("bar.sync %0, 64;" :: "r"((id) + 1) : "memory")

// ---------------- prep: permute + XOR-swizzle + tf32-convert weights -------
// Per chunk row (32 words per n): w_pre(k) = (k&3)*8 + (k>>2); vec4 group
// g = w_pre>>2 stored at g ^ (n&7).
__global__ void prep_kernel(const float* __restrict__ W1, const float* __restrict__ W2,
                            const float* __restrict__ W3) {
    int tid = blockIdx.x * blockDim.x + threadIdx.x;
    int stride = gridDim.x * blockDim.x;
    for (int i = tid; i < 12 * 256 * 32; i += stride) {
        int c = i >> 13, n = (i >> 5) & 255, k = i & 31;
        int w = ((k & 3) << 3) + (k >> 2);
        int word = (n << 5) + ((((w >> 2) ^ (n & 7)) << 2) | (w & 3));
        g_Wp1[c * PAN_BIG + word] = f2tf32(W1[(c * 32 + k) * 256 + n]);
    }
    for (int i = tid; i < 8 * 256 * 32; i += stride) {
        int c = i >> 13, n = (i >> 5) & 255, k = i & 31;
        int w = ((k & 3) << 3) + (k >> 2);
        int word = (n << 5) + ((((w >> 2) ^ (n & 7)) << 2) | (w & 3));
        g_Wp2[c * PAN_BIG + word] = f2tf32(W2[(c * 32 + k) * 256 + n]);
    }
    for (int i = tid; i < 8 * 64 * 32; i += stride) {
        int c = i >> 11, n = (i >> 5) & 63, k = i & 31;
        int w = ((k & 3) << 3) + (k >> 2);
        int word = (n << 5) + ((((w >> 2) ^ (n & 7)) << 2) | (w & 3));
        g_Wp3[c * PAN_SM + word] = f2tf32(W3[(c * 32 + k) * 64 + n]);
    }
}

// ---------------- 64x64 warp-tile mma over one 32-K chunk ------------------
// A: tf32 bits, fragment-major permuted, stride lda.  B: XOR-swizzled panel.
template <int NT>
__device__ __forceinline__ void mma_chunk3(const unsigned* __restrict__ Ab, int lda,
                                           const unsigned* __restrict__ Bp, int nbase,
                                           float acc[4][NT][4], int lane, int wm) {
    const int lr = lane >> 2, lc = lane & 3;
#pragma unroll
    for (int half = 0; half < 2; half++) {
        unsigned a[4][2][4];
#pragma unroll
        for (int mt = 0; mt < 4; mt++)
#pragma unroll
            for (int h = 0; h < 2; h++) {
                int row = wm + mt * 16 + h * 8 + lr;
                uint4 v = *reinterpret_cast<const uint4*>(Ab + row * lda + lc * 8 + half * 4);
                a[mt][h][0] = v.x; a[mt][h][1] = v.y; a[mt][h][2] = v.z; a[mt][h][3] = v.w;
            }
#pragma unroll
        for (int nt = 0; nt < NT; nt++) {
            const unsigned* bp = Bp + ((nbase + nt * 8 + lr) << 5)
                                    + (((2 * lc + half) ^ lr) << 2);
            uint4 b = *reinterpret_cast<const uint4*>(bp);
            unsigned bb[4] = {b.x, b.y, b.z, b.w};
#pragma unroll
            for (int ks = 0; ks < 2; ks++)
#pragma unroll
                for (int mt = 0; mt < 4; mt++)
                    mma8(acc[mt][nt],
                         a[mt][0][2 * ks], a[mt][1][2 * ks],
                         a[mt][0][2 * ks + 1], a[mt][1][2 * ks + 1],
                         bb[2 * ks], bb[2 * ks + 1]);
        }
    }
}

__device__ __forceinline__ int permpos(int c) {
    return (c & ~31) + ((c & 3) << 3) + ((c & 31) >> 2);
}

__device__ __forceinline__ void stats_from_acc(Smem& sm, float acc[4][8][4],
                                               const float* __restrict__ bias,
                                               int wm, int wn, int wcol, int lane) {
    const int lr = lane >> 2, lc = lane & 3;
#pragma unroll
    for (int mt = 0; mt < 4; mt++)
#pragma unroll
        for (int h = 0; h < 2; h++) {
            float s = 0.f, s2 = 0.f;
#pragma unroll
            for (int nt = 0; nt < 8; nt++) {
                int c = wn + nt * 8 + 2 * lc;
                float v0 = acc[mt][nt][2 * h]     + bias[c];
                float v1 = acc[mt][nt][2 * h + 1] + bias[c + 1];
                s += v0 + v1; s2 += v0 * v0 + v1 * v1;
            }
            s  += __shfl_xor_sync(0xffffffffu, s, 1);
            s2 += __shfl_xor_sync(0xffffffffu, s2, 1);
            s  += __shfl_xor_sync(0xffffffffu, s, 2);
            s2 += __shfl_xor_sync(0xffffffffu, s2, 2);
            if (lc == 0) {
                int row = wm + mt * 16 + h * 8 + lr;
                sm.red[row][wcol][0] = s;
                sm.red[row][wcol][1] = s2;
            }
        }
}

__device__ __forceinline__ void store_h_ln(Smem& sm, float acc[4][8][4],
                                           const float* __restrict__ bias,
                                           const float* __restrict__ g,
                                           const float* __restrict__ be,
                                           int wm, int wn, int lane) {
    const int lr = lane >> 2, lc = lane & 3;
    unsigned* Hu = sm.H;
#pragma unroll
    for (int mt = 0; mt < 4; mt++)
#pragma unroll
        for (int h = 0; h < 2; h++) {
            int row = wm + mt * 16 + h * 8 + lr;
            float s  = sm.red[row][0][0] + sm.red[row][1][0] + sm.red[row][2][0] + sm.red[row][3][0];
            float s2 = sm.red[row][0][1] + sm.red[row][1][1] + sm.red[row][2][1] + sm.red[row][3][1];
            float mu  = s * (1.f / 256.f);
            float var = fmaxf(s2 * (1.f / 256.f) - mu * mu, 0.f);
            float rsd = rsqrtf(var + 1e-5f);
            unsigned* Hrow = Hu + row * SH_LD;
#pragma unroll
            for (int nt = 0; nt < 8; nt++) {
                int c = wn + nt * 8 + 2 * lc;
                int p0 = permpos(c);
                float v0 = (acc[mt][nt][2 * h]     + bias[c]     - mu) * rsd * g[c]     + be[c];
                float v1 = (acc[mt][nt][2 * h + 1] + bias[c + 1] - mu) * rsd * g[c + 1] + be[c + 1];
                Hrow[p0]     = f2tf32(fmaxf(v0, 0.f));
                Hrow[p0 + 8] = f2tf32(fmaxf(v1, 0.f));
            }
        }
}

__global__ void __launch_bounds__(NTH, 1)
edge_mlp_kernel(const float* __restrict__ src, const float* __restrict__ dst,
                const float* __restrict__ ea, const float* __restrict__ u,
                const void* __restrict__ batch_raw, const float* __restrict__ wind,
                const float* __restrict__ Ww, const float* __restrict__ bw,
                const float* __restrict__ gw, const float* __restrict__ betaw,
                const float* __restrict__ b1, const float* __restrict__ g1,
                const float* __restrict__ beta1,
                const float* __restrict__ b2, const float* __restrict__ g2,
                const float* __restrict__ beta2,
                const float* __restrict__ b3,
                float* __restrict__ out) {
    extern __shared__ char smem_raw[];
    Smem& sm = *reinterpret_cast<Smem*>(smem_raw);

    const int tid  = threadIdx.x;
    const int lane = tid & 31;
    const int warp = tid >> 5;          // 0..7
    const int wcol = warp & 3;          // pair id / n-column
    const int wrow = warp >> 2;         // 0/1
    const int wm   = wrow * 64;
    const long long base = (long long)blockIdx.x * MT;

    // ---- pair-partitioned panel copy: pair wcol copies its own n-region ----
    auto cp_panel = [&](int p) {
        const unsigned* s;
        int region;                        // words per pair region
        if (p < 12)      { s = g_Wp1 + p * PAN_BIG;        region = 2048; }
        else if (p < 20) { s = g_Wp2 + (p - 12) * PAN_BIG; region = 2048; }
        else             { s = g_Wp3 + (p - 20) * PAN_SM;  region = 512;  }
        int half = region >> 1;
        int off  = wcol * region + wrow * half;
        const unsigned* sp = s + off;
        unsigned d = smem_u32(sm.Bp[p & 1]) + (unsigned)off * 4u;
        for (int i = lane * 4; i < half; i += 128)
            asm volatile("cp.async.cg.shared.global [%0], [%1], 16;"
                         :: "r"(d + (unsigned)i * 4u), "l"(sp + i));
        CPCOMMIT();
    };

    cp_panel(0);
    cp_panel(1);

    if (tid == 0) {
        const unsigned* p = reinterpret_cast<const unsigned*>(batch_raw);
        int f = 1;
        for (int i = 0; i < 64; i++) if (p[2 * i + 1] != 0u) { f = 0; break; }
        sm.is64 = f;
    }
    for (int i = tid; i < 256; i += NTH) sm.Ww[i] = Ww[i];
    for (int i = tid; i < 128; i += NTH) { sm.bw[i] = bw[i]; sm.gw[i] = gw[i]; sm.betaw[i] = betaw[i]; }
    for (int i = tid; i < 256; i += NTH) {
        sm.b1[i] = b1[i]; sm.g1[i] = g1[i]; sm.be1[i] = beta1[i];
        sm.b2[i] = b2[i]; sm.g2[i] = g2[i]; sm.be2[i] = beta2[i];
    }
    for (int i = tid; i < 64; i += NTH) sm.b3[i] = b3[i];
    __syncthreads();

    const int is64 = sm.is64;
    for (int r = tid; r < MT; r += NTH) {
        long long e = base + r;
        if (e < E_TOTAL) {
            sm.batch[r] = is64 ? (int)reinterpret_cast<const long long*>(batch_raw)[e]
                               : reinterpret_cast<const int*>(batch_raw)[e];
            sm.w0[r] = wind[2 * e];
            sm.w1[r] = wind[2 * e + 1];
        } else { sm.batch[r] = 0; sm.w0[r] = 0.f; sm.w1[r] = 0.f; }
    }
    __syncthreads();

    // winding-MLP LN stats (2 threads / row)
    {
        const int r = tid >> 1, q = tid & 1;
        const float a0 = sm.w0[r], a1 = sm.w1[r];
        float s = 0.f, s2 = 0.f;
#pragma unroll 4
        for (int jj = 0; jj < 64; jj++) {
            int j = q * 64 + jj;
            float t = fmaf(a0, sm.Ww[j], fmaf(a1, sm.Ww[128 + j], sm.bw[j]));
            s += t; s2 += t * t;
        }
        s  += __shfl_xor_sync(0xffffffffu, s, 1);
        s2 += __shfl_xor_sync(0xffffffffu, s2, 1);
        float mu  = s * (1.f / 128.f);
        float var = fmaxf(s2 * (1.f / 128.f) - mu * mu, 0.f);
        if (q == 0) { sm.mu_[r] = mu; sm.rs_[r] = rsqrtf(var + 1e-5f); }
    }
    __syncthreads();

    // ---- layer-1 A tiles: 3 buffers of [128 x 64] tf32 (permuted), alias H ----
    unsigned* Aw = sm.H;
    auto stageA = [&](int seg) {
        unsigned* A = Aw + (seg % 3) * SA_BUF;
        for (int i = tid; i < MT * 16; i += NTH) {
            int r = i >> 4, q = i & 15;   // 4 cols per item
            long long e = base + r;
            float4 v = make_float4(0.f, 0.f, 0.f, 0.f);
            if (e < E_TOTAL) {
                if (seg == 0)      v = *(const float4*)(src + e * 64 + q * 4);
                else if (seg == 1) v = *(const float4*)(dst + e * 64 + q * 4);
                else if (seg == 2) v = *(const float4*)(ea  + e * 64 + q * 4);
                else if (seg == 3) v = *(const float4*)(u + (long long)sm.batch[r] * 64 + q * 4);
                else {
                    int j0 = (seg - 4) * 64 + q * 4;
                    float vv[4];
#pragma unroll
                    for (int x = 0; x < 4; x++) {
                        int j = j0 + x;
                        float t2 = fmaf(sm.w0[r], sm.Ww[j], fmaf(sm.w1[r], sm.Ww[128 + j], sm.bw[j]));
                        vv[x] = fmaxf((t2 - sm.mu_[r]) * sm.rs_[r] * sm.gw[j] + sm.betaw[j], 0.f);
                    }
                    v = make_float4(vv[0], vv[1], vv[2], vv[3]);
                }
            }
            // permuted positions of cols 4q..4q+3 within the 64-wide tile
            unsigned* Ar = A + r * SA_LD;
            int c0 = q * 4;
#pragma unroll
            for (int x = 0; x < 4; x++) {
                int c = c0 + x;
                int pos = (c & 32) + ((c & 3) << 3) + ((c & 31) >> 2);
                Ar[pos] = f2tf32(x == 0 ? v.x : x == 1 ? v.y : x == 2 ? v.z : v.w);
            }
        }
    };
    stageA(0);
    stageA(1);

    float acc[4][8][4];
#pragma unroll
    for (int mt = 0; mt < 4; mt++)
#pragma unroll
        for (int nt = 0; nt < 8; nt++)
#pragma unroll
            for (int k = 0; k < 4; k++) acc[mt][nt][k] = 0.f;

    // =============== Layer 1: K=384, 12 chunks (tiles s=0..5) ===============
#pragma unroll
    for (int s = 0; s < 6; s++) {
        const unsigned* At = Aw + (s % 3) * SA_BUF;
        // even chunk t=2s (panel buf 0)
        CPWAIT1();
        __syncthreads();                  // A tile s + panel 2s visible; A buf (s+2)%3 free
        if (s < 4) stageA(s + 2);         // LDG latency hidden behind this chunk's mma
        mma_chunk3<8>(At, SA_LD, sm.Bp[0], wcol * 64, acc, lane, wm);
        PAIRBAR(wcol);
        cp_panel(2 * s + 2);
        // odd chunk t=2s+1 (panel buf 1)
        CPWAIT1();
        PAIRBAR(wcol);
        mma_chunk3<8>(At + 32, SA_LD, sm.Bp[1], wcol * 64, acc, lane, wm);
        PAIRBAR(wcol);
        cp_panel(2 * s + 3);
    }
    stats_from_acc(sm, acc, sm.b1, wm, wcol * 64, wcol, lane);
    __syncthreads();
    store_h_ln(sm, acc, sm.b1, sm.g1, sm.be1, wm, wcol * 64, lane);
    __syncthreads();

    // =============== Layer 2: K=256, 8 chunks (no CTA syncs) ===============
#pragma unroll
    for (int mt = 0; mt < 4; mt++)
#pragma unroll
        for (int nt = 0; nt < 8; nt++)
#pragma unroll
            for (int k = 0; k < 4; k++) acc[mt][nt][k] = 0.f;

#pragma unroll
    for (int t = 12; t < 20; t++) {
        CPWAIT1();
        PAIRBAR(wcol);
        mma_chunk3<8>(sm.H + (t - 12) * 32, SH_LD, sm.Bp[t & 1], wcol * 64, acc, lane, wm);
        PAIRBAR(wcol);
        cp_panel(t + 2);
    }
    stats_from_acc(sm, acc, sm.b2, wm, wcol * 64, wcol, lane);
    __syncthreads();
    store_h_ln(sm, acc, sm.b2, sm.g2, sm.be2, wm, wcol * 64, lane);
    __syncthreads();

    // =============== Layer 3: K=256, N=64, 8 chunks (no CTA syncs) ===============
    float acc3[4][2][4];
#pragma unroll
    for (int mt = 0; mt < 4; mt++)
#pragma unroll
        for (int nt = 0; nt < 2; nt++)
#pragma unroll
            for (int k = 0; k < 4; k++) acc3[mt][nt][k] = 0.f;

#pragma unroll
    for (int t = 20; t < 28; t++) {
        CPWAIT1();
        PAIRBAR(wcol);
        mma_chunk3<2>(sm.H + (t - 20) * 32, SH_LD, sm.Bp[t & 1], wcol * 16, acc3, lane, wm);
        PAIRBAR(wcol);
        if (t + 2 < 28) cp_panel(t + 2); else CPCOMMIT();
    }

    // output staging (unpermuted, stride 68 floats) over H, then coalesced store
    __syncthreads();       // all reads of H (h2) complete before overwrite
    {
        float* ob = reinterpret_cast<float*>(sm.H);
        const int lr = lane >> 2, lc = lane & 3;
#pragma unroll
        for (int mt = 0; mt < 4; mt++)
#pragma unroll
            for (int nt = 0; nt < 2; nt++) {
                int c = wcol * 16 + nt * 8 + 2 * lc;
#pragma unroll
                for (int h = 0; h < 2; h++) {
                    int r = wm + mt * 16 + lr + h * 8;
                    ob[r * 68 + c]     = acc3[mt][nt][2 * h]     + sm.b3[c];
                    ob[r * 68 + c + 1] = acc3[mt][nt][2 * h + 1] + sm.b3[c + 1];
                }
            }
    }
    __syncthreads();
    {
        const float* ob = reinterpret_cast<const float*>(sm.H);
        for (int i = tid; i < MT * 16; i += NTH) {
            int r = i >> 4, c4 = i & 15;
            long long e = base + r;
            if (e < E_TOTAL) {
                float4 v = *reinterpret_cast<const float4*>(ob + r * 68 + c4 * 4);
                *reinterpret_cast<float4*>(out + e * 64 + c4 * 4) = v;
            }
        }
    }
}

extern "C" void kernel_launch(void* const* d_in, const int* in_sizes, int n_in,
                              void* d_out, int out_size) {
    const float* src    = (const float*)d_in[0];
    const float* dst    = (const float*)d_in[1];
    const float* ea     = (const float*)d_in[2];
    const float* u      = (const float*)d_in[3];
    const void*  batch  = d_in[4];
    const float* wind   = (const float*)d_in[5];
    const float* Ww     = (const float*)d_in[6];
    const float* bw     = (const float*)d_in[7];
    const float* gw     = (const float*)d_in[8];
    const float* betaw  = (const float*)d_in[9];
    const float* W1     = (const float*)d_in[10];
    const float* b1     = (const float*)d_in[11];
    const float* g1     = (const float*)d_in[12];
    const float* beta1  = (const float*)d_in[13];
    const float* W2     = (const float*)d_in[14];
    const float* b2     = (const float*)d_in[15];
    const float* g2     = (const float*)d_in[16];
    const float* beta2  = (const float*)d_in[17];
    const float* W3     = (const float*)d_in[18];
    const float* b3     = (const float*)d_in[19];
    float* out = (float*)d_out;

    prep_kernel<<<296, 256>>>(W1, W2, W3);

    const int smem = (int)sizeof(Smem);
    cudaFuncSetAttribute(edge_mlp_kernel, cudaFuncAttributeMaxDynamicSharedMemorySize, smem);
    const int grid = (E_TOTAL + MT - 1) / MT;
    edge_mlp_kernel<<<grid, NTH, smem>>>(src, dst, ea, u, batch, wind,
                                         Ww, bw, gw, betaw,
                                         b1, g1, beta1,
                                         b2, g2, beta2,
                                         b3, out);
}